// round 13
// baseline (speedup 1.0000x reference)
#include <cuda_runtime.h>
#include <cstdint>

// Problem shapes (fixed by setup_inputs)
#define C_      500
#define G_      200
#define F_      500
#define NCLUST_ 10
#define NFRAG_  5000000
#define GF_     (G_ * F_)                 // 100,000
#define CG_     (C_ * G_)                 // 100,000
// Histogram: per (g,c) pair, 64 words, base = (g*C_+c)*64  (g-major:
// k_out blocks sweep contiguous 32KB regions — measured best in R11/R12).
// word = f & 63 (lane-major), nibble = f >> 6. Total 6.4M words = 25.6 MB.
#define CNT_WORDS_ (CG_ * 64)

#define U_BLOCKS_    250                          // 2000 warps: one per (k,g)
#define FRAG_T_      8                            // fragments per thread
#define FRAG_BLOCKS_ ((NFRAG_ / FRAG_T_ + 255) / 256)   // 2442

// log(n!) for n = 0..15
__constant__ float c_lf[16] = {
    0.0f, 0.0f, 0.6931472f, 1.7917595f, 3.1780539f, 4.7874917f,
    6.5792512f, 8.5251613f, 10.6046029f, 12.8018275f, 15.1044126f,
    17.5023078f, 19.9872145f, 22.5521639f, 25.1912212f, 27.8992714f };

// Scratch (device globals — statically zero-init; k_out re-zeroes g_cnt)
__device__ unsigned int g_cnt[CNT_WORDS_];              // 25.6 MB nibble histogram
__device__ __align__(16) float g_u[NCLUST_ * GF_];      // 4 MB: u[k][g*F+f]
__device__ float g_S[NCLUST_ * G_];                     // sum_f exp(u) per (k,g)
__device__ unsigned g_dummy[64];                        // sink for out-of-range c

// ---------------------------------------------------------------------------
// Kernel A: block-specialized. (Exact R11 form — measured best.)
//   blocks [0, U_BLOCKS_):    build u-table + exp-sums (warp per (k,g))
//   blocks [U_BLOCKS_, ...):  fragment histogram (pure nibble RED, 8/thread)
__global__ void kA(const float* __restrict__ bincounts,
                   const float* __restrict__ baseline,
                   const float* __restrict__ dw,
                   const float* __restrict__ cm,
                   const int*   __restrict__ genes_oi,
                   const int*   __restrict__ cgix,
                   const int*   __restrict__ binix) {
    if (blockIdx.x < U_BLOCKS_) {
        int warp = blockIdx.x * 8 + (threadIdx.x >> 5);   // = k*G_ + g, < 2000
        int lane = threadIdx.x & 31;
        int k = warp / G_;
        int g = warp - k * G_;
        float a  = dw[k];
        float b  = cm[k];
        int   go = genes_oi[g];
        const float* brow = bincounts + (size_t)g  * F_;
        const float* lrow = baseline  + (size_t)go * F_;
        float*       urow = g_u       + (size_t)warp * F_; // k*GF_ + g*F_
        float s = 0.0f;
        #pragma unroll 4
        for (int f = lane; f < F_; f += 32) {
            float u = fmaf(brow[f], a, lrow[f] + b);
            urow[f] = u;
            s += __expf(u);
        }
        #pragma unroll
        for (int o = 16; o; o >>= 1) s += __shfl_xor_sync(0xffffffffu, s, o);
        if (lane == 0) g_S[warp] = s;
    } else {
        unsigned i = (blockIdx.x - U_BLOCKS_) * 256 + threadIdx.x;
        if (i >= NFRAG_ / FRAG_T_) return;
        const int4* cg4p = reinterpret_cast<const int4*>(cgix) + i * 2;
        const int4* f4p  = reinterpret_cast<const int4*>(binix) + i * 2;
        int4 cgA = cg4p[0], cgB = cg4p[1];
        int4 fA  = f4p[0],  fB  = f4p[1];
        unsigned cgs[8] = {(unsigned)cgA.x, (unsigned)cgA.y, (unsigned)cgA.z, (unsigned)cgA.w,
                           (unsigned)cgB.x, (unsigned)cgB.y, (unsigned)cgB.z, (unsigned)cgB.w};
        unsigned fs[8]  = {(unsigned)fA.x,  (unsigned)fA.y,  (unsigned)fA.z,  (unsigned)fA.w,
                           (unsigned)fB.x,  (unsigned)fB.y,  (unsigned)fB.z,  (unsigned)fB.w};
        #pragma unroll
        for (int j = 0; j < 8; j++) {
            unsigned cg = cgs[j];
            unsigned f  = fs[j];
            unsigned c  = cg / (unsigned)G_;       // const-div -> mul/shift
            unsigned g  = cg - c * (unsigned)G_;
            unsigned w  = ((g * (unsigned)C_ + c) << 6) | (f & 63u);
            atomicAdd(&g_cnt[w], 1u << ((f >> 6) * 4u));
        }
    }
}

// ---------------------------------------------------------------------------
// Kernel B: bin sweep — R11 form + batch-0 count prefetch hoisted ahead of
// the shared-memory fill (the fill + barrier hides the first-batch L2
// latency). Otherwise identical: block per (g, chunk of 128 c's) -> 800
// blocks; 10 cluster u-rows in shared (stride-1, conflict-free); per-lane-
// replicated log-factorial from __constant__; lf-LDS predicated on n>=2;
// 4 c's per warp-batch (MLP=8, ILP=4), 4 batches; zero-write-back.
//   out[c,g] = sum_f (n*u - log(n!)) - S[k,g]
__global__ __launch_bounds__(256) void k_out(const int* __restrict__ labels,
                                             float*     __restrict__ out) {
    __shared__ __align__(16) float s_u[NCLUST_ * 512];   // padded rows; pad zeroed
    __shared__ float s_lfr[16 * 32];           // s_lfr[n*32+lane] = log(n!)
    __shared__ int   s_lab[128];
    __shared__ float s_S[NCLUST_];
    int tid   = threadIdx.x;
    int g     = blockIdx.x >> 2;
    int chunk = blockIdx.x & 3;
    int w = tid >> 5, lane = tid & 31;

    // ── batch-0 prefetch: 8 loads + 8 zero-stores in flight before the fill ──
    unsigned pre0A[4], pre0B[4];
    #pragma unroll
    for (int e = 0; e < 4; e++) {
        int c = chunk * 128 + w + 8 * e;       // batch b=0: ci = w + 8e
        unsigned* p = (c < C_) ? (g_cnt + (((size_t)g * C_ + c) << 6)) : g_dummy;
        pre0A[e] = p[lane];
        pre0B[e] = p[lane + 32];
        p[lane]      = 0u;
        p[lane + 32] = 0u;
    }

    // ── shared-memory fill (overlaps in-flight batch-0 loads) ──
    for (int i = tid; i < 512; i += 256) s_lfr[i] = c_lf[i >> 5];
    if (tid < NCLUST_) s_S[tid] = g_S[tid * G_ + g];
    if (tid < 128) {
        int c = chunk * 128 + tid;
        s_lab[tid] = labels[c < C_ ? c : C_ - 1];
    }
    if (tid < NCLUST_ * 12) {                  // zero pad tail [500,512)
        int k = tid / 12;
        s_u[k * 512 + 500 + (tid - k * 12)] = 0.0f;
    }
    for (int i = tid; i < NCLUST_ * 125; i += 256) {   // 500 floats = 125 float4
        int k  = i / 125;
        int f4 = i - k * 125;
        float4 v = reinterpret_cast<const float4*>(g_u + (size_t)k * GF_ + (size_t)g * F_)[f4];
        reinterpret_cast<float4*>(s_u + k * 512)[f4] = v;
    }
    __syncthreads();

    #pragma unroll
    for (int b = 0; b < 4; b++) {
        // 4 warp-uniform c's per batch: ci = w + 8e + 32b, covers 0..127
        int      cc[4]; int kk[4]; bool val[4];
        unsigned cw0[4], cw1[4];
        #pragma unroll
        for (int e = 0; e < 4; e++) {
            int ci = w + 32 * b + 8 * e;
            int c  = chunk * 128 + ci;
            val[e] = (c < C_);
            cc[e]  = c;
            kk[e]  = s_lab[ci];
            if (b == 0) {
                cw0[e] = pre0A[e];
                cw1[e] = pre0B[e];
            } else {
                unsigned* p = val[e] ? (g_cnt + (((size_t)g * C_ + c) << 6)) : g_dummy;
                cw0[e] = p[lane];
                cw1[e] = p[lane + 32];
                p[lane]      = 0u;
                p[lane + 32] = 0u;
            }
        }

        float acc[4] = {0.f, 0.f, 0.f, 0.f};
        #pragma unroll
        for (int j = 0; j < 8; j++) {
            #pragma unroll
            for (int e = 0; e < 4; e++) {
                const float* su = s_u + kk[e] * 512;
                unsigned n0 = (cw0[e] >> (4 * j)) & 15u;     // f = lane + 64j
                unsigned n1 = (cw1[e] >> (4 * j)) & 15u;     // f = lane + 32 + 64j
                float a = acc[e];
                a = fmaf((float)n0, su[lane + 64 * j], a);
                a = fmaf((float)n1, su[lane + 32 + 64 * j], a);
                if (n0 >= 2u) a -= s_lfr[n0 * 32 + lane];    // predicated, rare
                if (n1 >= 2u) a -= s_lfr[n1 * 32 + lane];
                acc[e] = a;
            }
        }
        #pragma unroll
        for (int o = 16; o; o >>= 1) {
            #pragma unroll
            for (int e = 0; e < 4; e++)
                acc[e] += __shfl_xor_sync(0xffffffffu, acc[e], o);
        }
        if (lane == 0) {
            #pragma unroll
            for (int e = 0; e < 4; e++)
                if (val[e]) out[cc[e] * G_ + g] = acc[e] - s_S[kk[e]];
        }
    }
}

// ---------------------------------------------------------------------------
extern "C" void kernel_launch(void* const* d_in, const int* in_sizes, int n_in,
                              void* d_out, int out_size) {
    const float* bincounts = (const float*)d_in[0];   // (G,F)
    const float* baseline  = (const float*)d_in[1];   // (N_GENES,F)
    const float* dw        = (const float*)d_in[2];   // (N_CLUST,1,1)
    const float* cm        = (const float*)d_in[3];   // (N_CLUST,)
    const int*   genes_oi  = (const int*)d_in[4];     // (G,)
    const int*   labels    = (const int*)d_in[5];     // (C,)
    const int*   cgix      = (const int*)d_in[6];     // (NFRAG,)
    const int*   binix     = (const int*)d_in[7];     // (NFRAG,)
    float*       out       = (float*)d_out;           // (C,G)

    (void)in_sizes; (void)n_in; (void)out_size;

    // A) fused prep + fragment histogram
    kA<<<U_BLOCKS_ + FRAG_BLOCKS_, 256>>>(bincounts, baseline, dw, cm,
                                          genes_oi, cgix, binix);
    // B) bin sweep -> out (also re-zeroes g_cnt): 200 g * 4 chunks of 128 c
    k_out<<<G_ * 4, 256>>>(labels, out);
}

// round 15
// speedup vs baseline: 1.3607x; 1.3607x over previous
#include <cuda_runtime.h>
#include <cstdint>

// Problem shapes (fixed by setup_inputs)
#define C_      500
#define G_      200
#define F_      500
#define NCLUST_ 10
#define NFRAG_  5000000
#define GF_     (G_ * F_)                 // 100,000
#define CG_     (C_ * G_)                 // 100,000
// Histogram: per (g,c) pair, 64 words, base = (g*C_+c)*64.
// word = f & 63 (lane-major), nibble = f >> 6. Total 6.4M words = 25.6 MB.
#define CNT_WORDS_ (CG_ * 64)

#define U_BLOCKS_    250                          // 2000 warps: one per (k,g)
#define FRAG_T_      8                            // fragments per thread
#define FRAG_BLOCKS_ ((NFRAG_ / FRAG_T_ + 255) / 256)   // 2442

// log(n!) for n = 0..15
__constant__ float c_lf[16] = {
    0.0f, 0.0f, 0.6931472f, 1.7917595f, 3.1780539f, 4.7874917f,
    6.5792512f, 8.5251613f, 10.6046029f, 12.8018275f, 15.1044126f,
    17.5023078f, 19.9872145f, 22.5521639f, 25.1912212f, 27.8992714f };

// Scratch (device globals — statically zero-init; k_out re-zeroes g_cnt)
__device__ unsigned int g_cnt[CNT_WORDS_];              // 25.6 MB nibble histogram
__device__ __align__(16) float g_u[NCLUST_ * GF_];      // 4 MB: u[k][g*F+f]
__device__ float g_S[NCLUST_ * G_];                     // sum_f exp(u) per (k,g)
__device__ unsigned g_dummy[64];                        // sink for out-of-range c

// ---------------------------------------------------------------------------
// Kernel A: block-specialized. (Plain index loads — __ldcs measured SLOWER.)
//   blocks [0, U_BLOCKS_):    build u-table + exp-sums (warp per (k,g))
//   blocks [U_BLOCKS_, ...):  fragment histogram (pure nibble RED, 8/thread)
__global__ void kA(const float* __restrict__ bincounts,
                   const float* __restrict__ baseline,
                   const float* __restrict__ dw,
                   const float* __restrict__ cm,
                   const int*   __restrict__ genes_oi,
                   const int*   __restrict__ cgix,
                   const int*   __restrict__ binix) {
    if (blockIdx.x < U_BLOCKS_) {
        int warp = blockIdx.x * 8 + (threadIdx.x >> 5);   // = k*G_ + g, < 2000
        int lane = threadIdx.x & 31;
        int k = warp / G_;
        int g = warp - k * G_;
        float a  = dw[k];
        float b  = cm[k];
        int   go = genes_oi[g];
        const float* brow = bincounts + (size_t)g  * F_;
        const float* lrow = baseline  + (size_t)go * F_;
        float*       urow = g_u       + (size_t)warp * F_; // k*GF_ + g*F_
        float s = 0.0f;
        #pragma unroll 4
        for (int f = lane; f < F_; f += 32) {
            float u = fmaf(brow[f], a, lrow[f] + b);
            urow[f] = u;
            s += __expf(u);
        }
        #pragma unroll
        for (int o = 16; o; o >>= 1) s += __shfl_xor_sync(0xffffffffu, s, o);
        if (lane == 0) g_S[warp] = s;
    } else {
        unsigned i = (blockIdx.x - U_BLOCKS_) * 256 + threadIdx.x;
        if (i >= NFRAG_ / FRAG_T_) return;
        const int4* cg4p = reinterpret_cast<const int4*>(cgix) + i * 2;
        const int4* f4p  = reinterpret_cast<const int4*>(binix) + i * 2;
        int4 cgA = cg4p[0], cgB = cg4p[1];
        int4 fA  = f4p[0],  fB  = f4p[1];
        unsigned cgs[8] = {(unsigned)cgA.x, (unsigned)cgA.y, (unsigned)cgA.z, (unsigned)cgA.w,
                           (unsigned)cgB.x, (unsigned)cgB.y, (unsigned)cgB.z, (unsigned)cgB.w};
        unsigned fs[8]  = {(unsigned)fA.x,  (unsigned)fA.y,  (unsigned)fA.z,  (unsigned)fA.w,
                           (unsigned)fB.x,  (unsigned)fB.y,  (unsigned)fB.z,  (unsigned)fB.w};
        #pragma unroll
        for (int j = 0; j < 8; j++) {
            unsigned cg = cgs[j];
            unsigned f  = fs[j];
            unsigned c  = cg / (unsigned)G_;       // const-div -> mul/shift
            unsigned g  = cg - c * (unsigned)G_;
            unsigned w  = ((g * (unsigned)C_ + c) << 6) | (f & 63u);
            atomicAdd(&g_cnt[w], 1u << ((f >> 6) * 4u));
        }
    }
}

// ---------------------------------------------------------------------------
// Kernel B: bin sweep — R10 form (measured best: 45.0us locked, issue 67%).
// Block per (g, chunk of 128 c's) -> 800 blocks. 10 cluster u-rows in shared
// (stride-1, conflict-free); per-lane-replicated log-factorial table from
// __constant__; lf-LDS predicated on n>=2 (rare). Warp handles 4 c's per
// batch (8 independent count loads = MLP, 4 accumulate chains = ILP),
// 4 batches. Zero-write-back for next graph replay.
//   out[c,g] = sum_f (n*u - log(n!)) - S[k,g]
__global__ __launch_bounds__(256) void k_out(const int* __restrict__ labels,
                                             float*     __restrict__ out) {
    __shared__ __align__(16) float s_u[NCLUST_ * 512];   // padded rows; pad zeroed
    __shared__ float s_lfr[16 * 32];           // s_lfr[n*32+lane] = log(n!)
    __shared__ int   s_lab[128];
    __shared__ float s_S[NCLUST_];
    int tid   = threadIdx.x;
    int g     = blockIdx.x >> 2;
    int chunk = blockIdx.x & 3;

    for (int i = tid; i < 512; i += 256) s_lfr[i] = c_lf[i >> 5];
    if (tid < NCLUST_) s_S[tid] = g_S[tid * G_ + g];
    if (tid < 128) {
        int c = chunk * 128 + tid;
        s_lab[tid] = labels[c < C_ ? c : C_ - 1];
    }
    if (tid < NCLUST_ * 12) {                  // zero pad tail [500,512)
        int k = tid / 12;
        s_u[k * 512 + 500 + (tid - k * 12)] = 0.0f;
    }
    for (int i = tid; i < NCLUST_ * 125; i += 256) {   // 500 floats = 125 float4
        int k  = i / 125;
        int f4 = i - k * 125;
        float4 v = reinterpret_cast<const float4*>(g_u + (size_t)k * GF_ + (size_t)g * F_)[f4];
        reinterpret_cast<float4*>(s_u + k * 512)[f4] = v;
    }
    __syncthreads();

    int w = tid >> 5, lane = tid & 31;
    #pragma unroll
    for (int b = 0; b < 4; b++) {
        // 4 warp-uniform c's per batch: ci = w + 8e + 32b, covers 0..127
        int      cc[4]; int kk[4]; bool val[4];
        unsigned* p[4];
        unsigned cw0[4], cw1[4];
        #pragma unroll
        for (int e = 0; e < 4; e++) {
            int ci = w + 32 * b + 8 * e;
            int c  = chunk * 128 + ci;
            val[e] = (c < C_);
            cc[e]  = c;
            kk[e]  = s_lab[ci];
            p[e]   = val[e] ? (g_cnt + (((size_t)g * C_ + c) << 6)) : g_dummy;
        }
        #pragma unroll
        for (int e = 0; e < 4; e++) { cw0[e] = p[e][lane]; cw1[e] = p[e][lane + 32]; }
        #pragma unroll
        for (int e = 0; e < 4; e++) { p[e][lane] = 0u; p[e][lane + 32] = 0u; }

        float acc[4] = {0.f, 0.f, 0.f, 0.f};
        #pragma unroll
        for (int j = 0; j < 8; j++) {
            #pragma unroll
            for (int e = 0; e < 4; e++) {
                const float* su = s_u + kk[e] * 512;
                unsigned n0 = (cw0[e] >> (4 * j)) & 15u;     // f = lane + 64j
                unsigned n1 = (cw1[e] >> (4 * j)) & 15u;     // f = lane + 32 + 64j
                float a = acc[e];
                a = fmaf((float)n0, su[lane + 64 * j], a);
                a = fmaf((float)n1, su[lane + 32 + 64 * j], a);
                if (n0 >= 2u) a -= s_lfr[n0 * 32 + lane];    // predicated, rare
                if (n1 >= 2u) a -= s_lfr[n1 * 32 + lane];
                acc[e] = a;
            }
        }
        #pragma unroll
        for (int o = 16; o; o >>= 1) {
            #pragma unroll
            for (int e = 0; e < 4; e++)
                acc[e] += __shfl_xor_sync(0xffffffffu, acc[e], o);
        }
        if (lane == 0) {
            #pragma unroll
            for (int e = 0; e < 4; e++)
                if (val[e]) out[cc[e] * G_ + g] = acc[e] - s_S[kk[e]];
        }
    }
}

// ---------------------------------------------------------------------------
extern "C" void kernel_launch(void* const* d_in, const int* in_sizes, int n_in,
                              void* d_out, int out_size) {
    const float* bincounts = (const float*)d_in[0];   // (G,F)
    const float* baseline  = (const float*)d_in[1];   // (N_GENES,F)
    const float* dw        = (const float*)d_in[2];   // (N_CLUST,1,1)
    const float* cm        = (const float*)d_in[3];   // (N_CLUST,)
    const int*   genes_oi  = (const int*)d_in[4];     // (G,)
    const int*   labels    = (const int*)d_in[5];     // (C,)
    const int*   cgix      = (const int*)d_in[6];     // (NFRAG,)
    const int*   binix     = (const int*)d_in[7];     // (NFRAG,)
    float*       out       = (float*)d_out;           // (C,G)

    (void)in_sizes; (void)n_in; (void)out_size;

    // A) fused prep + fragment histogram
    kA<<<U_BLOCKS_ + FRAG_BLOCKS_, 256>>>(bincounts, baseline, dw, cm,
                                          genes_oi, cgix, binix);
    // B) bin sweep -> out (also re-zeroes g_cnt): 200 g * 4 chunks of 128 c
    k_out<<<G_ * 4, 256>>>(labels, out);
}

// round 16
// speedup vs baseline: 1.3614x; 1.0006x over previous
#include <cuda_runtime.h>
#include <cstdint>

// Problem shapes (fixed by setup_inputs)
#define C_      500
#define G_      200
#define F_      500
#define NCLUST_ 10
#define NFRAG_  5000000
#define GF_     (G_ * F_)                 // 100,000
#define CG_     (C_ * G_)                 // 100,000
// Histogram: per (g,c) pair, 64 words, base = (g*C_+c)*64.
// word = f & 63 (lane-major), nibble = f >> 6. Total 6.4M words = 25.6 MB.
#define CNT_WORDS_ (CG_ * 64)

#define U_BLOCKS_    250                          // 2000 warps: one per (k,g)
#define FRAG_T_      8                            // fragments per thread
#define FRAG_BLOCKS_ ((NFRAG_ / FRAG_T_ + 255) / 256)   // 2442

// log(n!) for n = 0..15
__constant__ float c_lf[16] = {
    0.0f, 0.0f, 0.6931472f, 1.7917595f, 3.1780539f, 4.7874917f,
    6.5792512f, 8.5251613f, 10.6046029f, 12.8018275f, 15.1044126f,
    17.5023078f, 19.9872145f, 22.5521639f, 25.1912212f, 27.8992714f };

// Scratch (device globals — statically zero-init; k_out re-zeroes g_cnt)
__device__ unsigned int g_cnt[CNT_WORDS_];              // 25.6 MB nibble histogram
__device__ __align__(16) float g_u[NCLUST_ * GF_];      // 4 MB: u[k][g*F+f]
__device__ float g_S[NCLUST_ * G_];                     // sum_f exp(u) per (k,g)
__device__ unsigned g_dummy[64];                        // sink for out-of-range c

// ---------------------------------------------------------------------------
// Kernel A: block-specialized. (Byte-identical to R11/R14 — measured best.)
//   blocks [0, U_BLOCKS_):    build u-table + exp-sums (warp per (k,g))
//   blocks [U_BLOCKS_, ...):  fragment histogram (pure nibble RED, 8/thread)
__global__ void kA(const float* __restrict__ bincounts,
                   const float* __restrict__ baseline,
                   const float* __restrict__ dw,
                   const float* __restrict__ cm,
                   const int*   __restrict__ genes_oi,
                   const int*   __restrict__ cgix,
                   const int*   __restrict__ binix) {
    if (blockIdx.x < U_BLOCKS_) {
        int warp = blockIdx.x * 8 + (threadIdx.x >> 5);   // = k*G_ + g, < 2000
        int lane = threadIdx.x & 31;
        int k = warp / G_;
        int g = warp - k * G_;
        float a  = dw[k];
        float b  = cm[k];
        int   go = genes_oi[g];
        const float* brow = bincounts + (size_t)g  * F_;
        const float* lrow = baseline  + (size_t)go * F_;
        float*       urow = g_u       + (size_t)warp * F_; // k*GF_ + g*F_
        float s = 0.0f;
        #pragma unroll 4
        for (int f = lane; f < F_; f += 32) {
            float u = fmaf(brow[f], a, lrow[f] + b);
            urow[f] = u;
            s += __expf(u);
        }
        #pragma unroll
        for (int o = 16; o; o >>= 1) s += __shfl_xor_sync(0xffffffffu, s, o);
        if (lane == 0) g_S[warp] = s;
    } else {
        unsigned i = (blockIdx.x - U_BLOCKS_) * 256 + threadIdx.x;
        if (i >= NFRAG_ / FRAG_T_) return;
        const int4* cg4p = reinterpret_cast<const int4*>(cgix) + i * 2;
        const int4* f4p  = reinterpret_cast<const int4*>(binix) + i * 2;
        int4 cgA = cg4p[0], cgB = cg4p[1];
        int4 fA  = f4p[0],  fB  = f4p[1];
        unsigned cgs[8] = {(unsigned)cgA.x, (unsigned)cgA.y, (unsigned)cgA.z, (unsigned)cgA.w,
                           (unsigned)cgB.x, (unsigned)cgB.y, (unsigned)cgB.z, (unsigned)cgB.w};
        unsigned fs[8]  = {(unsigned)fA.x,  (unsigned)fA.y,  (unsigned)fA.z,  (unsigned)fA.w,
                           (unsigned)fB.x,  (unsigned)fB.y,  (unsigned)fB.z,  (unsigned)fB.w};
        #pragma unroll
        for (int j = 0; j < 8; j++) {
            unsigned cg = cgs[j];
            unsigned f  = fs[j];
            unsigned c  = cg / (unsigned)G_;       // const-div -> mul/shift
            unsigned g  = cg - c * (unsigned)G_;
            unsigned w  = ((g * (unsigned)C_ + c) << 6) | (f & 63u);
            atomicAdd(&g_cnt[w], 1u << ((f >> 6) * 4u));
        }
    }
}

// ---------------------------------------------------------------------------
// Kernel B: bin sweep — R11 decode schedule, 512-thread dual-chunk blocks.
// Block per (g, half): warps 0-7 sweep chunk 2*half, warps 8-15 chunk
// 2*half+1. Setup (20KB s_u + tables) amortized over 2 chunks; grid = 400
// blocks, all resident (3 blocks/SM by regs) -> single wave.
// Per warp: 4 c's per batch (MLP=8 loads, ILP=4 chains), 4 batches;
// stride-1 s_u LDS; per-lane-replicated lf, predicated on n>=2;
// zero-write-back for next graph replay.
//   out[c,g] = sum_f (n*u - log(n!)) - S[k,g]
__global__ __launch_bounds__(512) void k_out(const int* __restrict__ labels,
                                             float*     __restrict__ out) {
    __shared__ __align__(16) float s_u[NCLUST_ * 512];   // padded rows; pad zeroed
    __shared__ float s_lfr[16 * 32];           // s_lfr[n*32+lane] = log(n!)
    __shared__ int   s_lab[256];               // labels for both chunks
    __shared__ float s_S[NCLUST_];
    int tid  = threadIdx.x;
    int g    = blockIdx.x >> 1;
    int half = blockIdx.x & 1;

    s_lfr[tid & 511] = c_lf[(tid & 511) >> 5];         // 512 threads, one shot
    if (tid < NCLUST_) s_S[tid] = g_S[tid * G_ + g];
    if (tid < 256) {
        int c = half * 256 + tid;
        s_lab[tid] = labels[c < C_ ? c : C_ - 1];
    }
    if (tid < NCLUST_ * 12) {                  // zero pad tail [500,512)
        int k = tid / 12;
        s_u[k * 512 + 500 + (tid - k * 12)] = 0.0f;
    }
    for (int i = tid; i < NCLUST_ * 125; i += 512) {   // 500 floats = 125 float4
        int k  = i / 125;
        int f4 = i - k * 125;
        float4 v = reinterpret_cast<const float4*>(g_u + (size_t)k * GF_ + (size_t)g * F_)[f4];
        reinterpret_cast<float4*>(s_u + k * 512)[f4] = v;
    }
    __syncthreads();

    int w    = tid >> 5;                       // 0..15
    int lane = tid & 31;
    int w8   = w & 7;                          // warp-in-group
    int grp  = w >> 3;                         // 0 or 1: which chunk of this half
    int chunk = half * 2 + grp;                // 0..3
    int labbase = grp * 128;                   // offset into s_lab

    #pragma unroll
    for (int b = 0; b < 4; b++) {
        // 4 warp-uniform c's per batch: ci = w8 + 8e + 32b, covers 0..127
        int      cc[4]; int kk[4]; bool val[4];
        unsigned* p[4];
        unsigned cw0[4], cw1[4];
        #pragma unroll
        for (int e = 0; e < 4; e++) {
            int ci = w8 + 32 * b + 8 * e;
            int c  = chunk * 128 + ci;
            val[e] = (c < C_);
            cc[e]  = c;
            kk[e]  = s_lab[labbase + ci];
            p[e]   = val[e] ? (g_cnt + (((size_t)g * C_ + c) << 6)) : g_dummy;
        }
        #pragma unroll
        for (int e = 0; e < 4; e++) { cw0[e] = p[e][lane]; cw1[e] = p[e][lane + 32]; }
        #pragma unroll
        for (int e = 0; e < 4; e++) { p[e][lane] = 0u; p[e][lane + 32] = 0u; }

        float acc[4] = {0.f, 0.f, 0.f, 0.f};
        #pragma unroll
        for (int j = 0; j < 8; j++) {
            #pragma unroll
            for (int e = 0; e < 4; e++) {
                const float* su = s_u + kk[e] * 512;
                unsigned n0 = (cw0[e] >> (4 * j)) & 15u;     // f = lane + 64j
                unsigned n1 = (cw1[e] >> (4 * j)) & 15u;     // f = lane + 32 + 64j
                float a = acc[e];
                a = fmaf((float)n0, su[lane + 64 * j], a);
                a = fmaf((float)n1, su[lane + 32 + 64 * j], a);
                if (n0 >= 2u) a -= s_lfr[n0 * 32 + lane];    // predicated, rare
                if (n1 >= 2u) a -= s_lfr[n1 * 32 + lane];
                acc[e] = a;
            }
        }
        #pragma unroll
        for (int o = 16; o; o >>= 1) {
            #pragma unroll
            for (int e = 0; e < 4; e++)
                acc[e] += __shfl_xor_sync(0xffffffffu, acc[e], o);
        }
        if (lane == 0) {
            #pragma unroll
            for (int e = 0; e < 4; e++)
                if (val[e]) out[cc[e] * G_ + g] = acc[e] - s_S[kk[e]];
        }
    }
}

// ---------------------------------------------------------------------------
extern "C" void kernel_launch(void* const* d_in, const int* in_sizes, int n_in,
                              void* d_out, int out_size) {
    const float* bincounts = (const float*)d_in[0];   // (G,F)
    const float* baseline  = (const float*)d_in[1];   // (N_GENES,F)
    const float* dw        = (const float*)d_in[2];   // (N_CLUST,1,1)
    const float* cm        = (const float*)d_in[3];   // (N_CLUST,)
    const int*   genes_oi  = (const int*)d_in[4];     // (G,)
    const int*   labels    = (const int*)d_in[5];     // (C,)
    const int*   cgix      = (const int*)d_in[6];     // (NFRAG,)
    const int*   binix     = (const int*)d_in[7];     // (NFRAG,)
    float*       out       = (float*)d_out;           // (C,G)

    (void)in_sizes; (void)n_in; (void)out_size;

    // A) fused prep + fragment histogram
    kA<<<U_BLOCKS_ + FRAG_BLOCKS_, 256>>>(bincounts, baseline, dw, cm,
                                          genes_oi, cgix, binix);
    // B) bin sweep -> out (also re-zeroes g_cnt): 200 g * 2 halves of 256 c
    k_out<<<G_ * 2, 512>>>(labels, out);
}